// round 2
// baseline (speedup 1.0000x reference)
#include <cuda_runtime.h>
#include <cuda_bf16.h>
#include <cstdint>

#define N_TOKENS  16384
#define DIM       2048
#define NE        64
#define BM        128      // tokens per CTA
#define TK        32       // k-tile
#define THREADS   512
#define NKT       (DIM / TK)   // 64 k-tiles

// ---------- packed f32x2 helpers (SASS FFMA2 — PTX-only path) ----------
__device__ __forceinline__ unsigned long long pack2(float lo, float hi) {
    unsigned long long r;
    asm("mov.b64 %0, {%1, %2};" : "=l"(r) : "f"(lo), "f"(hi));
    return r;
}
__device__ __forceinline__ void unpack2(unsigned long long v, float& lo, float& hi) {
    asm("mov.b64 {%0, %1}, %2;" : "=f"(lo), "=f"(hi) : "l"(v));
}
__device__ __forceinline__ unsigned long long fma2(unsigned long long a,
                                                   unsigned long long b,
                                                   unsigned long long c) {
    unsigned long long d;
    asm("fma.rn.f32x2 %0, %1, %2, %3;" : "=l"(d) : "l"(a), "l"(b), "l"(c));
    return d;
}

struct SmemGemm {
    float xs[TK][BM];   // k-major x tile: 32*128*4 = 16 KB
    float ws[TK][NE];   // k-major W tile: 32*64*4  =  8 KB
};
struct Smem {
    union {
        SmemGemm g;
        float scores[BM][NE + 2];  // 128*66*4 = 33792 B (padded rows)
    };
};

__global__ void __launch_bounds__(THREADS, 1)
topk_gate_kernel(const float* __restrict__ x,
                 const float* __restrict__ W,
                 const float* __restrict__ b,
                 float* __restrict__ out) {
    __shared__ Smem smem;

    const int tid = threadIdx.x;
    const int tx  = tid & 15;        // expert group: 4 experts
    const int ty  = tid >> 4;        // token group: 4 tokens (0..31)
    const int m0  = blockIdx.x * BM;

    // 16 packed accumulators: [token-pair 0..1][expert 0..3]
    unsigned long long acc[2][4];
#pragma unroll
    for (int p = 0; p < 2; ++p)
#pragma unroll
        for (int j = 0; j < 4; ++j) acc[p][j] = 0ull;

    // ---------------- GEMM with register prefetch ----------------
    float4 xr[2];   // x tile prefetch: 1024 float4 / 512 thr = 2 each
    float4 wr;      // W tile prefetch: 512 float4 / 512 thr = 1 each

    auto load_tile = [&](int kt) {
        const int kb = kt * TK;
#pragma unroll
        for (int l = 0; l < 2; ++l) {
            const int i   = tid + l * THREADS;
            const int row = i >> 3;       // 0..127
            const int q   = i & 7;        // 0..7 (float4 within 32 floats)
            xr[l] = *(const float4*)&x[(size_t)(m0 + row) * DIM + kb + q * 4];
        }
        {
            const int row = tid >> 3;     // 0..63
            const int q   = tid & 7;
            wr = *(const float4*)&W[(size_t)row * DIM + kb + q * 4];
        }
    };
    auto store_tile = [&]() {
#pragma unroll
        for (int l = 0; l < 2; ++l) {
            const int i   = tid + l * THREADS;
            const int row = i >> 3;
            const int q   = i & 7;
            smem.g.xs[q * 4 + 0][row] = xr[l].x;
            smem.g.xs[q * 4 + 1][row] = xr[l].y;
            smem.g.xs[q * 4 + 2][row] = xr[l].z;
            smem.g.xs[q * 4 + 3][row] = xr[l].w;
        }
        {
            const int row = tid >> 3;
            const int q   = tid & 7;
            smem.g.ws[q * 4 + 0][row] = wr.x;
            smem.g.ws[q * 4 + 1][row] = wr.y;
            smem.g.ws[q * 4 + 2][row] = wr.z;
            smem.g.ws[q * 4 + 3][row] = wr.w;
        }
    };

    load_tile(0);
    store_tile();
    __syncthreads();

    for (int kt = 0; kt < NKT; ++kt) {
        if (kt + 1 < NKT) load_tile(kt + 1);

#pragma unroll
        for (int k = 0; k < TK; ++k) {
            const float* xrow = &smem.g.xs[k][ty * 4];
            unsigned long long xv0 = *(const unsigned long long*)(xrow);
            unsigned long long xv1 = *(const unsigned long long*)(xrow + 2);
            float4 w4 = *(const float4*)&smem.g.ws[k][tx * 4];
            unsigned long long wb0 = pack2(w4.x, w4.x);
            unsigned long long wb1 = pack2(w4.y, w4.y);
            unsigned long long wb2 = pack2(w4.z, w4.z);
            unsigned long long wb3 = pack2(w4.w, w4.w);
            acc[0][0] = fma2(xv0, wb0, acc[0][0]);
            acc[0][1] = fma2(xv0, wb1, acc[0][1]);
            acc[0][2] = fma2(xv0, wb2, acc[0][2]);
            acc[0][3] = fma2(xv0, wb3, acc[0][3]);
            acc[1][0] = fma2(xv1, wb0, acc[1][0]);
            acc[1][1] = fma2(xv1, wb1, acc[1][1]);
            acc[1][2] = fma2(xv1, wb2, acc[1][2]);
            acc[1][3] = fma2(xv1, wb3, acc[1][3]);
        }
        __syncthreads();
        if (kt + 1 < NKT) store_tile();
        __syncthreads();
    }

    // ---------------- write scores (+bias) to smem ----------------
    const int e0 = tx * 4;
    const int t0 = ty * 4;
#pragma unroll
    for (int j = 0; j < 4; ++j) {
        const float bj = __ldg(&b[e0 + j]);
#pragma unroll
        for (int p = 0; p < 2; ++p) {
            float sa, sb;
            unpack2(acc[p][j], sa, sb);
            smem.scores[t0 + 2 * p + 0][e0 + j] = sa + bj;
            smem.scores[t0 + 2 * p + 1][e0 + j] = sb + bj;
        }
    }
    __syncthreads();

    // ---------------- epilogue: top-2 + softmax renorm ----------------
    const int wid  = tid >> 5;   // 16 warps
    const int lane = tid & 31;

#pragma unroll
    for (int i = 0; i < BM / 16; ++i) {     // 8 tokens per warp
        const int t = wid * 8 + i;
        float s0 = smem.scores[t][lane];
        float s1 = smem.scores[t][lane + 32];

        float hi = fmaxf(s0, s1);
        float lo = fminf(s0, s1);
#pragma unroll
        for (int off = 16; off > 0; off >>= 1) {
            float ohi = __shfl_xor_sync(0xFFFFFFFFu, hi, off);
            float olo = __shfl_xor_sync(0xFFFFFFFFu, lo, off);
            float mx = fmaxf(hi, ohi);
            float mn = fminf(hi, ohi);
            float l2 = fmaxf(lo, olo);
            hi = mx;
            lo = fmaxf(mn, l2);
        }
        // hi = top1 score, lo = top2 score (global max m = hi)
        const float m  = hi;
        const float e0v = expf(s0 - m);
        const float e1v = expf(s1 - m);
        float z = e0v + e1v;
#pragma unroll
        for (int off = 16; off > 0; off >>= 1)
            z += __shfl_xor_sync(0xFFFFFFFFu, z, off);

        // out_i = e^(s_i - m) / (e^(top1-m) + e^(top2-m) + 1e-8 * Z_m)
        const float denom = 1.0f + expf(lo - m) + 1e-8f * z;
        const float inv   = 1.0f / denom;
        const float w0 = (s0 >= lo) ? e0v * inv : 0.0f;
        const float w1 = (s1 >= lo) ? e1v * inv : 0.0f;

        float* orow = out + (size_t)(m0 + t) * NE;
        orow[lane]      = w0;
        orow[lane + 32] = w1;
    }
}

extern "C" void kernel_launch(void* const* d_in, const int* in_sizes, int n_in,
                              void* d_out, int out_size) {
    const float* x = (const float*)d_in[0];
    const float* W = (const float*)d_in[1];
    const float* b = (const float*)d_in[2];
    float* out = (float*)d_out;
    topk_gate_kernel<<<N_TOKENS / BM, THREADS>>>(x, W, b, out);
}

// round 4
// speedup vs baseline: 1.1791x; 1.1791x over previous
#include <cuda_runtime.h>
#include <cuda_bf16.h>
#include <cstdint>

#define N_TOKENS  16384
#define DIM       2048
#define NE        64
#define BM        128      // tokens per CTA
#define TK        32       // k-tile
#define THREADS   512
#define NKT       (DIM / TK)   // 64 k-tiles
#define KQ        8            // k-steps per warp-quarter per tile

typedef unsigned long long ull;

// ---------- packed f32x2 helpers (SASS FFMA2 — PTX-only path) ----------
__device__ __forceinline__ ull pack2(float lo, float hi) {
    ull r;
    asm("mov.b64 %0, {%1, %2};" : "=l"(r) : "f"(lo), "f"(hi));
    return r;
}
__device__ __forceinline__ void unpack2(ull v, float& lo, float& hi) {
    asm("mov.b64 {%0, %1}, %2;" : "=f"(lo), "=f"(hi) : "l"(v));
}
__device__ __forceinline__ ull fma2(ull a, ull b, ull c) {
    ull d;
    asm("fma.rn.f32x2 %0, %1, %2, %3;" : "=l"(d) : "l"(a), "l"(b), "l"(c));
    return d;
}

struct SmemGemm {
    float xs[TK][BM];   // k-major x tile: 32*128*4 = 16 KB
    float ws[TK][NE];   // k-major W tile: 32*64*4  =  8 KB
};
struct Smem {
    union {
        SmemGemm g;
        float scores[BM][NE + 2];  // 128*66*4 = 33792 B (padded rows)
    };
};

__global__ void __launch_bounds__(THREADS, 1)
topk_gate_kernel(const float* __restrict__ x,
                 const float* __restrict__ W,
                 const float* __restrict__ b,
                 float* __restrict__ out) {
    __shared__ Smem smem;

    const int tid  = threadIdx.x;
    const int lane = tid & 31;
    const int wid  = tid >> 5;       // 16 warps
    const int kq   = wid & 3;        // k-quarter within tile (0..3)
    const int tg   = wid >> 2;       // token super-group (0..3)
    const int eg   = lane >> 2;      // expert group (0..7) -> 8 experts
    const int tq   = lane & 3;       // token sub-group (0..3) -> 8 tokens
    const int t0   = tg * 32 + tq * 8;
    const int e0   = eg * 8;
    const int m0   = blockIdx.x * BM;

    // accumulators: 8 tokens x 4 expert-pairs (fp32x2 over experts)
    ull acc[8][4];
#pragma unroll
    for (int t = 0; t < 8; ++t)
#pragma unroll
        for (int ep = 0; ep < 4; ++ep) acc[t][ep] = 0ull;

    // ---------------- tile load machinery (global -> reg -> smem) ----------------
    float4 xr[2];   // x tile prefetch: 1024 float4 / 512 thr = 2 each
    float4 wr;      // W tile prefetch: 512 float4 / 512 thr = 1 each

    auto load_tile = [&](int kt) {
        const int kb = kt * TK;
#pragma unroll
        for (int l = 0; l < 2; ++l) {
            const int i   = tid + l * THREADS;
            const int row = i >> 3;       // 0..127
            const int q   = i & 7;        // float4 within 32 floats
            xr[l] = *(const float4*)&x[(size_t)(m0 + row) * DIM + kb + q * 4];
        }
        {
            const int row = tid >> 3;     // 0..63
            const int q   = tid & 7;
            wr = *(const float4*)&W[(size_t)row * DIM + kb + q * 4];
        }
    };
    auto store_tile = [&]() {
#pragma unroll
        for (int l = 0; l < 2; ++l) {
            const int i   = tid + l * THREADS;
            const int row = i >> 3;
            const int q   = i & 7;
            smem.g.xs[q * 4 + 0][row] = xr[l].x;
            smem.g.xs[q * 4 + 1][row] = xr[l].y;
            smem.g.xs[q * 4 + 2][row] = xr[l].z;
            smem.g.xs[q * 4 + 3][row] = xr[l].w;
        }
        {
            const int row = tid >> 3;
            const int q   = tid & 7;
            smem.g.ws[q * 4 + 0][row] = wr.x;
            smem.g.ws[q * 4 + 1][row] = wr.y;
            smem.g.ws[q * 4 + 2][row] = wr.z;
            smem.g.ws[q * 4 + 3][row] = wr.w;
        }
    };

    load_tile(0);
    store_tile();
    __syncthreads();

    // ---------------- GEMM: T=8 tokens x E=8 experts per thread, k split 4-way ----------------
    for (int kt = 0; kt < NKT; ++kt) {
        if (kt + 1 < NKT) load_tile(kt + 1);

#pragma unroll
        for (int k = 0; k < KQ; ++k) {
            const int kk = kq * KQ + k;

            // W: 8 experts = 2x LDS.128, used directly as 4 f32x2 pairs
            ulonglong2 wpa = *(const ulonglong2*)&smem.g.ws[kk][e0];
            ulonglong2 wpb = *(const ulonglong2*)&smem.g.ws[kk][e0 + 4];
            ull wp[4] = { wpa.x, wpa.y, wpb.x, wpb.y };

            // x: 8 tokens = 2x LDS.128, each value duplicated into f32x2
            float4 xa = *(const float4*)&smem.g.xs[kk][t0];
            float4 xb = *(const float4*)&smem.g.xs[kk][t0 + 4];
            ull xd[8];
            xd[0] = pack2(xa.x, xa.x); xd[1] = pack2(xa.y, xa.y);
            xd[2] = pack2(xa.z, xa.z); xd[3] = pack2(xa.w, xa.w);
            xd[4] = pack2(xb.x, xb.x); xd[5] = pack2(xb.y, xb.y);
            xd[6] = pack2(xb.z, xb.z); xd[7] = pack2(xb.w, xb.w);

#pragma unroll
            for (int t = 0; t < 8; ++t)
#pragma unroll
                for (int ep = 0; ep < 4; ++ep)
                    acc[t][ep] = fma2(xd[t], wp[ep], acc[t][ep]);
        }
        __syncthreads();
        if (kt + 1 < NKT) store_tile();
        __syncthreads();
    }

    // ---------------- reduce k-split partials into smem scores ----------------
    // init with bias
    for (int i = tid; i < BM * NE; i += THREADS) {
        const int t = i >> 6;
        const int e = i & 63;
        smem.scores[t][e] = __ldg(&b[e]);
    }
    __syncthreads();

#pragma unroll
    for (int q = 0; q < 4; ++q) {
        if (kq == q) {
#pragma unroll
            for (int t = 0; t < 8; ++t)
#pragma unroll
                for (int ep = 0; ep < 4; ++ep) {
                    float sa, sb;
                    unpack2(acc[t][ep], sa, sb);
                    smem.scores[t0 + t][e0 + 2 * ep + 0] += sa;
                    smem.scores[t0 + t][e0 + 2 * ep + 1] += sb;
                }
        }
        __syncthreads();
    }

    // ---------------- epilogue: top-2 + softmax renorm ----------------
#pragma unroll
    for (int i = 0; i < BM / 16; ++i) {     // 8 tokens per warp
        const int t = wid * 8 + i;
        float s0 = smem.scores[t][lane];
        float s1 = smem.scores[t][lane + 32];

        float hi = fmaxf(s0, s1);
        float lo = fminf(s0, s1);
#pragma unroll
        for (int off = 16; off > 0; off >>= 1) {
            float ohi = __shfl_xor_sync(0xFFFFFFFFu, hi, off);
            float olo = __shfl_xor_sync(0xFFFFFFFFu, lo, off);
            float mx = fmaxf(hi, ohi);
            float mn = fminf(hi, ohi);
            float l2 = fmaxf(lo, olo);
            hi = mx;
            lo = fmaxf(mn, l2);
        }
        // hi = top1 score, lo = top2 score (global max m = hi)
        const float m   = hi;
        const float e0v = expf(s0 - m);
        const float e1v = expf(s1 - m);
        float z = e0v + e1v;
#pragma unroll
        for (int off = 16; off > 0; off >>= 1)
            z += __shfl_xor_sync(0xFFFFFFFFu, z, off);

        // out_i = e^(s_i - m) / (e^(top1-m) + e^(top2-m) + 1e-8 * Z_m)
        const float denom = 1.0f + expf(lo - m) + 1e-8f * z;
        const float inv   = 1.0f / denom;
        const float w0 = (s0 >= lo) ? e0v * inv : 0.0f;
        const float w1 = (s1 >= lo) ? e1v * inv : 0.0f;

        float* orow = out + (size_t)(m0 + t) * NE;
        orow[lane]      = w0;
        orow[lane + 32] = w1;
    }
}

extern "C" void kernel_launch(void* const* d_in, const int* in_sizes, int n_in,
                              void* d_out, int out_size) {
    const float* x = (const float*)d_in[0];
    const float* W = (const float*)d_in[1];
    const float* b = (const float*)d_in[2];
    float* out = (float*)d_out;
    topk_gate_kernel<<<N_TOKENS / BM, THREADS>>>(x, W, b, out);
}

// round 9
// speedup vs baseline: 1.9826x; 1.6814x over previous
#include <cuda_runtime.h>
#include <cuda_bf16.h>
#include <cstdint>

#define N_TOKENS  16384
#define DIM       2048
#define NE        64
#define BM        128            // tokens per CTA
#define KT        64             // k per tile
#define NTILES    (DIM / KT)     // 32
#define THREADS   256
#define PK        72             // padded k per smem row (bf16 elems)
#define ROWB      (PK * 2)       // 144 bytes per row
#define PK32      (PK / 2)       // uint32 stride per row

// per-stage layout (3 split levels for A and B)
#define OFF_A1    0
#define OFF_A2    (OFF_A1 + BM * ROWB)   // 18432
#define OFF_A3    (OFF_A2 + BM * ROWB)   // 36864
#define OFF_B1    (OFF_A3 + BM * ROWB)   // 55296
#define OFF_B2    (OFF_B1 + NE * ROWB)   // 64512
#define OFF_B3    (OFF_B2 + NE * ROWB)   // 73728
#define STAGE_SZ  (OFF_B3 + NE * ROWB)   // 82944
#define OFF_BIAS  (2 * STAGE_SZ)         // 165888
#define SMEM_TOTAL (OFF_BIAS + 256)      // 166144
#define SC_PITCH  68                     // scores float pitch (conflict-free)

typedef uint32_t u32;

__device__ __forceinline__ void mma16816(float* d, const u32* a, const u32* b) {
    asm volatile(
        "mma.sync.aligned.m16n8k16.row.col.f32.bf16.bf16.f32 "
        "{%0,%1,%2,%3}, {%4,%5,%6,%7}, {%8,%9}, {%0,%1,%2,%3};"
        : "+f"(d[0]), "+f"(d[1]), "+f"(d[2]), "+f"(d[3])
        : "r"(a[0]), "r"(a[1]), "r"(a[2]), "r"(a[3]), "r"(b[0]), "r"(b[1]));
}

__device__ __forceinline__ u32 bits2(__nv_bfloat162 v) { return *(u32*)&v; }

// 3-way bf16 split of a float2 (exact residuals: Sterbenz)
__device__ __forceinline__ void split3(float2 f, u32& o1, u32& o2, u32& o3) {
    __nv_bfloat162 h1 = __float22bfloat162_rn(f);
    float2 g1 = __bfloat1622float2(h1);
    float2 r1 = make_float2(f.x - g1.x, f.y - g1.y);
    __nv_bfloat162 h2 = __float22bfloat162_rn(r1);
    float2 g2 = __bfloat1622float2(h2);
    float2 r2 = make_float2(r1.x - g2.x, r1.y - g2.y);
    __nv_bfloat162 h3 = __float22bfloat162_rn(r2);
    o1 = bits2(h1); o2 = bits2(h2); o3 = bits2(h3);
}

__global__ void __launch_bounds__(THREADS, 1)
topk_gate_hmma(const float* __restrict__ x, const float* __restrict__ W,
               const float* __restrict__ b, float* __restrict__ out) {
    extern __shared__ char smem[];
    const int tid  = threadIdx.x;
    const int lane = tid & 31;
    const int wid  = tid >> 5;          // 8 warps
    const int m0   = blockIdx.x * BM;

    // tile-load geometry
    const int rb = tid >> 4;            // 0..15
    const int q  = tid & 15;            // float4 column

    float* bias = (float*)(smem + OFF_BIAS);
    if (tid < NE) bias[tid] = b[tid];

    float4 xr[8], wr[4];
    auto ldg_tile = [&](int t) {
        const int k0 = t * KT + q * 4;
#pragma unroll
        for (int l = 0; l < 8; ++l)
            xr[l] = *(const float4*)&x[(size_t)(m0 + rb + l * 16) * DIM + k0];
#pragma unroll
        for (int l = 0; l < 4; ++l)
            wr[l] = *(const float4*)&W[(size_t)(rb + l * 16) * DIM + k0];
    };

    auto split3_store = [&](float4 v, char* r1, char* r2, char* r3, int byteoff) {
        u32 a1, a2, a3, b1, b2, b3;
        split3(make_float2(v.x, v.y), a1, a2, a3);
        split3(make_float2(v.z, v.w), b1, b2, b3);
        *(uint2*)(r1 + byteoff) = make_uint2(a1, b1);
        *(uint2*)(r2 + byteoff) = make_uint2(a2, b2);
        *(uint2*)(r3 + byteoff) = make_uint2(a3, b3);
    };

    // MMA geometry
    const int g   = lane >> 2;
    const int tig = lane & 3;
    const int mw  = wid * 16;
    const int ai0 = (mw + g) * PK32;
    const int ai1 = (mw + g + 8) * PK32;

    float acc[8][4];
#pragma unroll
    for (int j = 0; j < 8; ++j)
#pragma unroll
        for (int r = 0; r < 4; ++r) acc[j][r] = 0.0f;

    ldg_tile(0);

    for (int t = 0; t < NTILES; ++t) {
        char* stg = smem + (t & 1) * STAGE_SZ;

        // ---- convert regs -> smem bf16 x3 levels
#pragma unroll
        for (int l = 0; l < 8; ++l)
            split3_store(xr[l], stg + OFF_A1, stg + OFF_A2, stg + OFF_A3,
                         (rb + l * 16) * ROWB + q * 8);
#pragma unroll
        for (int l = 0; l < 4; ++l)
            split3_store(wr[l], stg + OFF_B1, stg + OFF_B2, stg + OFF_B3,
                         (rb + l * 16) * ROWB + q * 8);

        if (t + 1 < NTILES) ldg_tile(t + 1);
        __syncthreads();

        // ---- HMMA: 16 tokens x 64 experts per warp, 6 split-products
        const u32* A1 = (const u32*)(stg + OFF_A1);
        const u32* A2 = (const u32*)(stg + OFF_A2);
        const u32* A3 = (const u32*)(stg + OFF_A3);
        const u32* B1 = (const u32*)(stg + OFF_B1);
        const u32* B2 = (const u32*)(stg + OFF_B2);
        const u32* B3 = (const u32*)(stg + OFF_B3);

#pragma unroll
        for (int ks = 0; ks < 4; ++ks) {
            const int o0 = ks * 8 + tig;
            const int o4 = o0 + 4;
            u32 a1[4], a2[4], a3[4];
            a1[0] = A1[ai0 + o0]; a1[1] = A1[ai1 + o0];
            a1[2] = A1[ai0 + o4]; a1[3] = A1[ai1 + o4];
            a2[0] = A2[ai0 + o0]; a2[1] = A2[ai1 + o0];
            a2[2] = A2[ai0 + o4]; a2[3] = A2[ai1 + o4];
            a3[0] = A3[ai0 + o0]; a3[1] = A3[ai1 + o0];
            a3[2] = A3[ai0 + o4]; a3[3] = A3[ai1 + o4];
#pragma unroll
            for (int j = 0; j < 8; ++j) {
                const int ni = (j * 8 + g) * PK32;
                u32 b1[2], b2[2], b3[2];
                b1[0] = B1[ni + o0]; b1[1] = B1[ni + o4];
                b2[0] = B2[ni + o0]; b2[1] = B2[ni + o4];
                b3[0] = B3[ni + o0]; b3[1] = B3[ni + o4];
                mma16816(acc[j], a1, b1);
                mma16816(acc[j], a1, b2);
                mma16816(acc[j], a2, b1);
                mma16816(acc[j], a2, b2);
                mma16816(acc[j], a1, b3);
                mma16816(acc[j], a3, b1);
            }
        }
        // no trailing barrier: next convert writes the other stage
    }
    __syncthreads();

    // ---------------- scores -> smem (aliases stage 0), + bias ----------------
    float* sc = (float*)smem;   // [BM][SC_PITCH] = 34816 B < STAGE_SZ
#pragma unroll
    for (int j = 0; j < 8; ++j) {
        const int n0 = j * 8 + 2 * tig;
        sc[(mw + g) * SC_PITCH + n0]         = acc[j][0] + bias[n0];
        sc[(mw + g) * SC_PITCH + n0 + 1]     = acc[j][1] + bias[n0 + 1];
        sc[(mw + g + 8) * SC_PITCH + n0]     = acc[j][2] + bias[n0];
        sc[(mw + g + 8) * SC_PITCH + n0 + 1] = acc[j][3] + bias[n0 + 1];
    }
    __syncthreads();

    // ---------------- per-token top-2 + softmax renorm ----------------
    if (tid < BM) {
        const float* row = &sc[tid * SC_PITCH];
        float s[64];
        float m1 = -1e30f, m2 = -1e30f;
#pragma unroll
        for (int e = 0; e < 64; ++e) {
            const float v = row[e];
            s[e] = v;
            if (v > m1) { m2 = m1; m1 = v; }
            else if (v > m2) { m2 = v; }
        }
        float z = 0.0f;
#pragma unroll
        for (int e = 0; e < 64; ++e) z += __expf(s[e] - m1);

        const float denom = 1.0f + __expf(m2 - m1) + 1e-8f * z;
        const float inv   = 1.0f / denom;

        float* orow = out + (size_t)(m0 + tid) * NE;
#pragma unroll
        for (int e4 = 0; e4 < 16; ++e4) {
            float4 o;
            o.x = (s[e4 * 4 + 0] >= m2) ? __expf(s[e4 * 4 + 0] - m1) * inv : 0.0f;
            o.y = (s[e4 * 4 + 1] >= m2) ? __expf(s[e4 * 4 + 1] - m1) * inv : 0.0f;
            o.z = (s[e4 * 4 + 2] >= m2) ? __expf(s[e4 * 4 + 2] - m1) * inv : 0.0f;
            o.w = (s[e4 * 4 + 3] >= m2) ? __expf(s[e4 * 4 + 3] - m1) * inv : 0.0f;
            *(float4*)&orow[e4 * 4] = o;
        }
    }
}

extern "C" void kernel_launch(void* const* d_in, const int* in_sizes, int n_in,
                              void* d_out, int out_size) {
    const float* x = (const float*)d_in[0];
    const float* W = (const float*)d_in[1];
    const float* b = (const float*)d_in[2];
    float* out = (float*)d_out;
    static int configured = 0;
    if (!configured) {
        cudaFuncSetAttribute(topk_gate_hmma,
                             cudaFuncAttributeMaxDynamicSharedMemorySize, SMEM_TOTAL);
        configured = 1;
    }
    topk_gate_hmma<<<N_TOKENS / BM, THREADS, SMEM_TOTAL>>>(x, W, b, out);
}